// round 8
// baseline (speedup 1.0000x reference)
#include <cuda_runtime.h>
#include <cuda_bf16.h>

#define NVX 50000
#define NEX 10000
#define HD  256
#define PX  400000

// ---------------- scratch (static device globals; no runtime alloc) ----------------
__device__ float g_ve[(size_t)NVX * HD];   // relu(v @ W1^T + b1) * n_weight
__device__ float g_ev[(size_t)NEX * HD];   // relu(e_out @ W2^T + b2) * e_weight
__device__ __nv_bfloat16 g_vh[(size_t)NVX * HD], g_vl[(size_t)NVX * HD];  // split of v
__device__ __nv_bfloat16 g_eh[(size_t)NEX * HD], g_el[(size_t)NEX * HD];  // split of e_out
__device__ __nv_bfloat16 g_w1h[HD * HD], g_w1l[HD * HD];
__device__ __nv_bfloat16 g_w2h[HD * HD], g_w2l[HD * HD];
__device__ int g_cnt_e[NEX];
__device__ int g_off_e[NEX + 1];
__device__ int g_cur_e[NEX];
__device__ int g_perm_e[PX];
__device__ int g_cnt_v[NVX];
__device__ int g_off_v[NVX + 1];
__device__ int g_cur_v[NVX];
__device__ int g_perm_v[PX];

__device__ __forceinline__ unsigned pack_bf16(float x0, float x1) {
    __nv_bfloat16 h0 = __float2bfloat16(x0);
    __nv_bfloat16 h1 = __float2bfloat16(x1);
    return (unsigned)__bfloat16_as_ushort(h0) | ((unsigned)__bfloat16_as_ushort(h1) << 16);
}

// ---------------- operand split passes ----------------
__global__ void k_split_v(const float* __restrict__ v) {
    size_t i = ((size_t)blockIdx.x * blockDim.x + threadIdx.x) * 4;
    if (i >= (size_t)NVX * HD) return;
    float4 x = *(const float4*)&v[i];
    float h0 = __bfloat162float(__float2bfloat16(x.x));
    float h1 = __bfloat162float(__float2bfloat16(x.y));
    float h2 = __bfloat162float(__float2bfloat16(x.z));
    float h3 = __bfloat162float(__float2bfloat16(x.w));
    uint2 hi = make_uint2(pack_bf16(h0, h1), pack_bf16(h2, h3));
    uint2 lo = make_uint2(pack_bf16(x.x - h0, x.y - h1), pack_bf16(x.z - h2, x.w - h3));
    *(uint2*)&g_vh[i] = hi;
    *(uint2*)&g_vl[i] = lo;
}

__global__ void k_split_w(const float* __restrict__ W1, const float* __restrict__ W2) {
    int t = blockIdx.x * blockDim.x + threadIdx.x;          // 0 .. 2*HD*HD/4-1
    const int per = HD * HD / 4;
    const float* src = (t < per) ? W1 : W2;
    __nv_bfloat16* dh = (t < per) ? g_w1h : g_w2h;
    __nv_bfloat16* dl = (t < per) ? g_w1l : g_w2l;
    size_t i = (size_t)(t < per ? t : t - per) * 4;
    float4 x = *(const float4*)&src[i];
    float h0 = __bfloat162float(__float2bfloat16(x.x));
    float h1 = __bfloat162float(__float2bfloat16(x.y));
    float h2 = __bfloat162float(__float2bfloat16(x.z));
    float h3 = __bfloat162float(__float2bfloat16(x.w));
    *(uint2*)&dh[i] = make_uint2(pack_bf16(h0, h1), pack_bf16(h2, h3));
    *(uint2*)&dl[i] = make_uint2(pack_bf16(x.x - h0, x.y - h1), pack_bf16(x.z - h2, x.w - h3));
}

// ---------------- CSR build (fused edge+vertex) ----------------
__global__ void k_zero_all() {
    int i = blockIdx.x * blockDim.x + threadIdx.x;
    if (i < NEX) g_cnt_e[i] = 0;
    if (i < NVX) g_cnt_v[i] = 0;
}

__global__ void k_hist_all(const int* __restrict__ eidx, const int* __restrict__ vidx) {
    int i = blockIdx.x * blockDim.x + threadIdx.x;
    if (i < PX) {
        atomicAdd(&g_cnt_e[eidx[i]], 1);
        atomicAdd(&g_cnt_v[vidx[i]], 1);
    }
}

__global__ void k_scan_all() {
    const bool EDGE = (blockIdx.x == 0);
    const int n = EDGE ? NEX : NVX;
    const int items = (n + 1023) / 1024;
    const int* cnt = EDGE ? g_cnt_e : g_cnt_v;
    int* off = EDGE ? g_off_e : g_off_v;
    int* cur = EDGE ? g_cur_e : g_cur_v;

    __shared__ int wsum[32];
    int t = threadIdx.x;            // blockDim.x == 1024
    int lane = t & 31, wid = t >> 5;
    int start = t * items;
    int end = min(start + items, n);

    int sum = 0;
    for (int i = start; i < end; i++) sum += cnt[i];

    int v = sum;
#pragma unroll
    for (int s = 1; s < 32; s <<= 1) {
        int y = __shfl_up_sync(0xffffffffu, v, s);
        if (lane >= s) v += y;
    }
    if (lane == 31) wsum[wid] = v;
    __syncthreads();
    if (wid == 0) {
        int w = wsum[lane];
        int vi = w;
#pragma unroll
        for (int s = 1; s < 32; s <<= 1) {
            int y = __shfl_up_sync(0xffffffffu, vi, s);
            if (lane >= s) vi += y;
        }
        wsum[lane] = vi - w;
    }
    __syncthreads();

    int excl = wsum[wid] + (v - sum);
    int run = excl;
    for (int i = start; i < end; i++) {
        off[i] = run;
        cur[i] = run;
        run += cnt[i];
    }
    if (t == 1023) off[n] = run;
}

__global__ void k_fill_all(const int* __restrict__ eidx, const int* __restrict__ vidx) {
    int i = blockIdx.x * blockDim.x + threadIdx.x;
    if (i < PX) {
        int pe = atomicAdd(&g_cur_e[eidx[i]], 1);
        g_perm_e[pe] = i;
        int pv = atomicAdd(&g_cur_v[vidx[i]], 1);
        g_perm_v[pv] = i;
    }
}

// ---------------- split-bf16 tensor-core GEMM, cp.async + ldmatrix ----------
// C[m,n] = relu(sum_k A[m,k]*B[n,k] + bias[n]) * rowscale[m]
// A,B pre-split to bf16 hi/lo; C = Ah*Bh + Ah*Bl + Al*Bh (fp32 accum).
#define BM 128
#define BN 128
#define BK 32
#define SP 20            // smem row stride in b32 (16 data + 4 pad); 80B stride ->
                         // ldmatrix 8-row groups hit all 32 banks conflict-free
#define SMEM_BYTES (8 * BM * SP * 4)   // 2 buffers x 4 arrays x BM*SP u32 = 81920B

__device__ __forceinline__ void mma_bf16(float* c, const unsigned* a, const unsigned* b) {
    asm volatile(
        "mma.sync.aligned.m16n8k16.row.col.f32.bf16.bf16.f32 "
        "{%0,%1,%2,%3}, {%4,%5,%6,%7}, {%8,%9}, {%0,%1,%2,%3};"
        : "+f"(c[0]), "+f"(c[1]), "+f"(c[2]), "+f"(c[3])
        : "r"(a[0]), "r"(a[1]), "r"(a[2]), "r"(a[3]), "r"(b[0]), "r"(b[1]));
}

__device__ __forceinline__ void cp16(unsigned* dst, const void* src) {
    unsigned s = (unsigned)__cvta_generic_to_shared(dst);
    asm volatile("cp.async.cg.shared.global [%0], [%1], 16;" :: "r"(s), "l"(src));
}

__device__ __forceinline__ void ldsm4(unsigned* r, const unsigned* p) {
    unsigned a = (unsigned)__cvta_generic_to_shared(p);
    asm volatile("ldmatrix.sync.aligned.m8n8.x4.shared.b16 {%0,%1,%2,%3}, [%4];"
        : "=r"(r[0]), "=r"(r[1]), "=r"(r[2]), "=r"(r[3]) : "r"(a));
}

__device__ __forceinline__ void ldsm2(unsigned* r, const unsigned* p) {
    unsigned a = (unsigned)__cvta_generic_to_shared(p);
    asm volatile("ldmatrix.sync.aligned.m8n8.x2.shared.b16 {%0,%1}, [%2];"
        : "=r"(r[0]), "=r"(r[1]) : "r"(a));
}

template <bool VE>
__global__ void __launch_bounds__(256, 2)
k_gemm_bf16(const float* __restrict__ bias, const float* __restrict__ rowscale, int M) {
    const __nv_bfloat16* __restrict__ Ah = VE ? g_vh : g_eh;
    const __nv_bfloat16* __restrict__ Al = VE ? g_vl : g_el;
    const __nv_bfloat16* __restrict__ Bh = VE ? g_w1h : g_w2h;
    const __nv_bfloat16* __restrict__ Bl = VE ? g_w1l : g_w2l;
    float* C = VE ? g_ve : g_ev;

    extern __shared__ unsigned smem_u[];
    unsigned* sA_hi = smem_u;                    // [2][BM*SP]
    unsigned* sA_lo = smem_u + 2 * BM * SP;
    unsigned* sB_hi = smem_u + 4 * BM * SP;
    unsigned* sB_lo = smem_u + 6 * BM * SP;

    const int tid = threadIdx.x;
    const int bm = blockIdx.x * BM;
    const int bn = blockIdx.y * BN;
    const int wid = tid >> 5, lane = tid & 31;
    const int gid = lane >> 2, tid4 = lane & 3;
    const int wm = (wid & 1) * 64;
    const int wn = (wid >> 1) * 32;

    // ldmatrix per-lane source rows/cols
    const int aRow = lane & 15;                 // row within 16-row fragment
    const int aCol = (lane >> 4) * 4;           // k-half (u32 offset 0 / 4)
    const int bRow = lane & 7;                  // row within 8-row fragment
    const int bCol = ((lane >> 3) & 1) * 4;     // k-half for lanes 0..15 (16+ unused)

    const int crow = tid >> 1;
    const int csg = (tid & 1) * 2;
    const int gmc = min(bm + crow, M - 1);       // clamp (excess rows computed, not stored)
    const size_t aBase = (size_t)gmc * HD + csg * 8;
    const size_t bBase = (size_t)(bn + crow) * HD + csg * 8;
    const int dOff = crow * SP + csg * 4;

    float acc[4][4][4];
#pragma unroll
    for (int mt = 0; mt < 4; mt++)
#pragma unroll
        for (int nt = 0; nt < 4; nt++)
#pragma unroll
            for (int q = 0; q < 4; q++) acc[mt][nt][q] = 0.f;

#define CP_STAGE(KT, BUF)                                                     \
    {                                                                         \
        int bo = (BUF) * BM * SP + dOff;                                      \
        size_t ka = aBase + (KT) * BK;                                        \
        size_t kb = bBase + (KT) * BK;                                        \
        cp16(&sA_hi[bo], Ah + ka);     cp16(&sA_hi[bo + 4], Ah + ka + 8);     \
        cp16(&sA_lo[bo], Al + ka);     cp16(&sA_lo[bo + 4], Al + ka + 8);     \
        cp16(&sB_hi[bo], Bh + kb);     cp16(&sB_hi[bo + 4], Bh + kb + 8);     \
        cp16(&sB_lo[bo], Bl + kb);     cp16(&sB_lo[bo + 4], Bl + kb + 8);     \
    }

#define COMPUTE_TILE(BUF)                                                     \
    {                                                                         \
        const unsigned* pAh = sA_hi + (BUF) * BM * SP;                        \
        const unsigned* pAl = sA_lo + (BUF) * BM * SP;                        \
        const unsigned* pBh = sB_hi + (BUF) * BM * SP;                        \
        const unsigned* pBl = sB_lo + (BUF) * BM * SP;                        \
        _Pragma("unroll")                                                     \
        for (int ks = 0; ks < 2; ks++) {                                      \
            unsigned ah[4][4], al[4][4];                                      \
            _Pragma("unroll")                                                 \
            for (int mt = 0; mt < 4; mt++) {                                  \
                int ao = (wm + mt * 16 + aRow) * SP + ks * 8 + aCol;          \
                ldsm4(ah[mt], pAh + ao);                                      \
                ldsm4(al[mt], pAl + ao);                                      \
            }                                                                 \
            _Pragma("unroll")                                                 \
            for (int nt = 0; nt < 4; nt++) {                                  \
                int bo2 = (wn + nt * 8 + bRow) * SP + ks * 8 + bCol;          \
                unsigned bh[2], bl[2];                                        \
                ldsm2(bh, pBh + bo2);                                         \
                ldsm2(bl, pBl + bo2);                                         \
                _Pragma("unroll")                                             \
                for (int mt = 0; mt < 4; mt++) {                              \
                    mma_bf16(acc[mt][nt], ah[mt], bh);                        \
                    mma_bf16(acc[mt][nt], ah[mt], bl);                        \
                    mma_bf16(acc[mt][nt], al[mt], bh);                        \
                }                                                             \
            }                                                                 \
        }                                                                     \
    }

    CP_STAGE(0, 0);
    asm volatile("cp.async.commit_group;");
#pragma unroll
    for (int kt = 0; kt < HD / BK; kt++) {
        if (kt + 1 < HD / BK) CP_STAGE(kt + 1, (kt + 1) & 1);
        asm volatile("cp.async.commit_group;");
        asm volatile("cp.async.wait_group 1;");
        __syncthreads();
        COMPUTE_TILE(kt & 1);
        __syncthreads();
    }

#undef CP_STAGE
#undef COMPUTE_TILE

    // ---- epilogue: bias + relu + rowscale ----
#pragma unroll
    for (int mt = 0; mt < 4; mt++) {
        int rm0 = bm + wm + mt * 16 + gid;
        int rm1 = rm0 + 8;
        float sc0 = (rm0 < M) ? rowscale[rm0] : 0.f;
        float sc1 = (rm1 < M) ? rowscale[rm1] : 0.f;
#pragma unroll
        for (int nt = 0; nt < 4; nt++) {
            int cn = bn + wn + nt * 8 + tid4 * 2;
            float b0f = bias[cn], b1f = bias[cn + 1];
            if (rm0 < M) {
                float2 o;
                o.x = fmaxf(acc[mt][nt][0] + b0f, 0.f) * sc0;
                o.y = fmaxf(acc[mt][nt][1] + b1f, 0.f) * sc0;
                *(float2*)&C[(size_t)rm0 * HD + cn] = o;
            }
            if (rm1 < M) {
                float2 o;
                o.x = fmaxf(acc[mt][nt][2] + b0f, 0.f) * sc1;
                o.y = fmaxf(acc[mt][nt][3] + b1f, 0.f) * sc1;
                *(float2*)&C[(size_t)rm1 * HD + cn] = o;
            }
        }
    }
}

// ---------------- warp-per-row pull-based accumulation (no smem, no barriers) ----
// e_out[j,:] = (e[j,:] + sum g_ve[pairs_v[p],:]*nrw[p]) / ers[j]; emits bf16 split.
__global__ void k_edge_accum(const float* __restrict__ e, const int* __restrict__ pairs_v,
                             const float* __restrict__ nrw, const float* __restrict__ ers,
                             float* __restrict__ e_out) {
    int j = (blockIdx.x * blockDim.x + threadIdx.x) >> 5;
    int lane = threadIdx.x & 31;
    if (j >= NEX) return;
    int s = g_off_e[j], t = g_off_e[j + 1];

    const float4* e4 = (const float4*)&e[(size_t)j * HD];
    float4 a0 = e4[lane * 2], a1 = e4[lane * 2 + 1];

    for (int c = s; c < t; c += 32) {
        int i = c + lane;
        int row = 0; float w = 0.f;
        if (i < t) {
            int p = g_perm_e[i];
            row = pairs_v[p];
            w = nrw[p];
        }
        int m = min(32, t - c);
#pragma unroll 4
        for (int q = 0; q < m; q++) {
            int r = __shfl_sync(0xffffffffu, row, q);
            float wq = __shfl_sync(0xffffffffu, w, q);
            const float4* src = (const float4*)&g_ve[(size_t)r * HD];
            float4 x0 = src[lane * 2], x1 = src[lane * 2 + 1];
            a0.x = fmaf(x0.x, wq, a0.x); a0.y = fmaf(x0.y, wq, a0.y);
            a0.z = fmaf(x0.z, wq, a0.z); a0.w = fmaf(x0.w, wq, a0.w);
            a1.x = fmaf(x1.x, wq, a1.x); a1.y = fmaf(x1.y, wq, a1.y);
            a1.z = fmaf(x1.z, wq, a1.z); a1.w = fmaf(x1.w, wq, a1.w);
        }
    }

    float inv = 1.f / ers[j];
    a0.x *= inv; a0.y *= inv; a0.z *= inv; a0.w *= inv;
    a1.x *= inv; a1.y *= inv; a1.z *= inv; a1.w *= inv;

    float4* o4 = (float4*)&e_out[(size_t)j * HD];
    o4[lane * 2] = a0; o4[lane * 2 + 1] = a1;

    // bf16 hi/lo split for GEMM2 input
    float h[8] = {a0.x, a0.y, a0.z, a0.w, a1.x, a1.y, a1.z, a1.w};
    float hr[8];
#pragma unroll
    for (int q = 0; q < 8; q++) hr[q] = __bfloat162float(__float2bfloat16(h[q]));
    uint4 hv = make_uint4(pack_bf16(h[0], h[1]), pack_bf16(h[2], h[3]),
                          pack_bf16(h[4], h[5]), pack_bf16(h[6], h[7]));
    uint4 lv = make_uint4(pack_bf16(h[0] - hr[0], h[1] - hr[1]),
                          pack_bf16(h[2] - hr[2], h[3] - hr[3]),
                          pack_bf16(h[4] - hr[4], h[5] - hr[5]),
                          pack_bf16(h[6] - hr[6], h[7] - hr[7]));
    *(uint4*)&g_eh[(size_t)j * HD + lane * 8] = hv;
    *(uint4*)&g_el[(size_t)j * HD + lane * 8] = lv;
}

// v_out[i,:] = (v[i,:]*nw[i] + sum g_ev[pairs_e[p],:]*erw[p]) / nrs[i]
__global__ void k_vertex_accum(const float* __restrict__ v, const int* __restrict__ pairs_e,
                               const float* __restrict__ erw, const float* __restrict__ nrs,
                               const float* __restrict__ nw, float* __restrict__ v_out) {
    int i0 = (blockIdx.x * blockDim.x + threadIdx.x) >> 5;
    int lane = threadIdx.x & 31;
    if (i0 >= NVX) return;
    int s = g_off_v[i0], t = g_off_v[i0 + 1];

    float nwi = nw[i0];
    const float4* v4 = (const float4*)&v[(size_t)i0 * HD];
    float4 a0 = v4[lane * 2], a1 = v4[lane * 2 + 1];
    a0.x *= nwi; a0.y *= nwi; a0.z *= nwi; a0.w *= nwi;
    a1.x *= nwi; a1.y *= nwi; a1.z *= nwi; a1.w *= nwi;

    for (int c = s; c < t; c += 32) {
        int i = c + lane;
        int row = 0; float w = 0.f;
        if (i < t) {
            int p = g_perm_v[i];
            row = pairs_e[p];
            w = erw[p];
        }
        int m = min(32, t - c);
#pragma unroll 4
        for (int q = 0; q < m; q++) {
            int r = __shfl_sync(0xffffffffu, row, q);
            float wq = __shfl_sync(0xffffffffu, w, q);
            const float4* src = (const float4*)&g_ev[(size_t)r * HD];
            float4 x0 = src[lane * 2], x1 = src[lane * 2 + 1];
            a0.x = fmaf(x0.x, wq, a0.x); a0.y = fmaf(x0.y, wq, a0.y);
            a0.z = fmaf(x0.z, wq, a0.z); a0.w = fmaf(x0.w, wq, a0.w);
            a1.x = fmaf(x1.x, wq, a1.x); a1.y = fmaf(x1.y, wq, a1.y);
            a1.z = fmaf(x1.z, wq, a1.z); a1.w = fmaf(x1.w, wq, a1.w);
        }
    }

    float inv = 1.f / nrs[i0];
    a0.x *= inv; a0.y *= inv; a0.z *= inv; a0.w *= inv;
    a1.x *= inv; a1.y *= inv; a1.z *= inv; a1.w *= inv;

    float4* o4 = (float4*)&v_out[(size_t)i0 * HD];
    o4[lane * 2] = a0; o4[lane * 2 + 1] = a1;
}

// ---------------- launcher: R6 fork/join topology (best measured), launches only ----
static cudaStream_t g_s1 = nullptr;
static cudaEvent_t g_evFork = nullptr, g_evCsr = nullptr;

extern "C" void kernel_launch(void* const* d_in, const int* in_sizes, int n_in,
                              void* d_out, int out_size) {
    const float* v            = (const float*)d_in[0];
    const float* e            = (const float*)d_in[1];
    const float* W1           = (const float*)d_in[2];
    const float* b1           = (const float*)d_in[3];
    const float* W2           = (const float*)d_in[4];
    const float* b2           = (const float*)d_in[5];
    const float* n_weight     = (const float*)d_in[6];
    const float* e_weight     = (const float*)d_in[7];
    const float* n_reg_weight = (const float*)d_in[8];
    const float* e_reg_weight = (const float*)d_in[9];
    const float* e_reg_sum    = (const float*)d_in[10];
    const float* n_reg_sum    = (const float*)d_in[11];
    const int*   pairs_v      = (const int*)d_in[12];
    const int*   eidx         = (const int*)d_in[13];
    const int*   pairs_e      = (const int*)d_in[14];
    const int*   vidx         = (const int*)d_in[15];

    float* v_out = (float*)d_out;                              // [NVX, HD]
    float* e_out = (float*)d_out + (size_t)NVX * HD;           // [NEX, HD]

    if (!g_s1) {   // one-time setup on the uncaptured correctness call
        cudaStreamCreateWithFlags(&g_s1, cudaStreamNonBlocking);
        cudaEventCreateWithFlags(&g_evFork, cudaEventDisableTiming);
        cudaEventCreateWithFlags(&g_evCsr, cudaEventDisableTiming);
        cudaFuncSetAttribute(k_gemm_bf16<true>,
                             cudaFuncAttributeMaxDynamicSharedMemorySize, SMEM_BYTES);
        cudaFuncSetAttribute(k_gemm_bf16<false>,
                             cudaFuncAttributeMaxDynamicSharedMemorySize, SMEM_BYTES);
    }

    // main: operand splits (GEMM1 prerequisites)
    k_split_v<<<(NVX * HD / 4 + 255) / 256, 256>>>(v);                       // #1
    k_split_w<<<(2 * HD * HD / 4 + 255) / 256, 256>>>(W1, W2);               // #2

    // fork CSR chain onto s1
    cudaEventRecord(g_evFork, 0);
    cudaStreamWaitEvent(g_s1, g_evFork, 0);
    k_zero_all<<<(NVX + 255) / 256, 256, 0, g_s1>>>();                       // #3

    // GEMM1 (4th submitted launch -> ncu sample window)
    dim3 g1((NVX + BM - 1) / BM, HD / BN);
    k_gemm_bf16<true><<<g1, 256, SMEM_BYTES>>>(b1, n_weight, NVX);           // #4

    k_hist_all<<<(PX + 255) / 256, 256, 0, g_s1>>>(eidx, vidx);              // #5
    k_scan_all<<<2, 1024, 0, g_s1>>>();                                      // #6
    k_fill_all<<<(PX + 255) / 256, 256, 0, g_s1>>>(eidx, vidx);              // #7

    // join CSR into main before the accums
    cudaEventRecord(g_evCsr, g_s1);
    cudaStreamWaitEvent(0, g_evCsr, 0);

    k_edge_accum<<<(NEX + 7) / 8, 256>>>(e, pairs_v, n_reg_weight, e_reg_sum, e_out);   // #8

    dim3 g2((NEX + BM - 1) / BM, HD / BN);
    k_gemm_bf16<false><<<g2, 256, SMEM_BYTES>>>(b2, e_weight, NEX);          // #9

    k_vertex_accum<<<(NVX + 7) / 8, 256>>>(v, pairs_e, e_reg_weight, n_reg_sum, n_weight, v_out); // #10
}

// round 9
// speedup vs baseline: 1.5274x; 1.5274x over previous
#include <cuda_runtime.h>
#include <cuda_bf16.h>

#define NVX 50000
#define NEX 10000
#define HD  256
#define PX  400000

// ---------------- scratch (static device globals; no runtime alloc) ----------------
__device__ float g_ve[(size_t)NVX * HD];   // relu(v @ W1^T + b1) * n_weight
__device__ float g_ev[(size_t)NEX * HD];   // relu(e_out @ W2^T + b2) * e_weight
__device__ __nv_bfloat16 g_vh[(size_t)NVX * HD], g_vl[(size_t)NVX * HD];  // split of v
__device__ __nv_bfloat16 g_eh[(size_t)NEX * HD], g_el[(size_t)NEX * HD];  // split of e_out
__device__ __nv_bfloat16 g_w1h[HD * HD], g_w1l[HD * HD];
__device__ __nv_bfloat16 g_w2h[HD * HD], g_w2l[HD * HD];
__device__ int g_cnt_e[NEX];
__device__ int g_off_e[NEX + 1];
__device__ int g_cur_e[NEX];
__device__ int g_perm_e[PX];
__device__ int g_cnt_v[NVX];
__device__ int g_off_v[NVX + 1];
__device__ int g_cur_v[NVX];
__device__ int g_perm_v[PX];

__device__ __forceinline__ unsigned pack_bf16(float x0, float x1) {
    __nv_bfloat16 h0 = __float2bfloat16(x0);
    __nv_bfloat16 h1 = __float2bfloat16(x1);
    return (unsigned)__bfloat16_as_ushort(h0) | ((unsigned)__bfloat16_as_ushort(h1) << 16);
}

// ---------------- operand split passes ----------------
__global__ void k_split_v(const float* __restrict__ v) {
    size_t i = ((size_t)blockIdx.x * blockDim.x + threadIdx.x) * 4;
    if (i >= (size_t)NVX * HD) return;
    float4 x = *(const float4*)&v[i];
    float h0 = __bfloat162float(__float2bfloat16(x.x));
    float h1 = __bfloat162float(__float2bfloat16(x.y));
    float h2 = __bfloat162float(__float2bfloat16(x.z));
    float h3 = __bfloat162float(__float2bfloat16(x.w));
    uint2 hi = make_uint2(pack_bf16(h0, h1), pack_bf16(h2, h3));
    uint2 lo = make_uint2(pack_bf16(x.x - h0, x.y - h1), pack_bf16(x.z - h2, x.w - h3));
    *(uint2*)&g_vh[i] = hi;
    *(uint2*)&g_vl[i] = lo;
}

__global__ void k_split_w(const float* __restrict__ W1, const float* __restrict__ W2) {
    int t = blockIdx.x * blockDim.x + threadIdx.x;          // 0 .. 2*HD*HD/4-1
    const int per = HD * HD / 4;
    const float* src = (t < per) ? W1 : W2;
    __nv_bfloat16* dh = (t < per) ? g_w1h : g_w2h;
    __nv_bfloat16* dl = (t < per) ? g_w1l : g_w2l;
    size_t i = (size_t)(t < per ? t : t - per) * 4;
    float4 x = *(const float4*)&src[i];
    float h0 = __bfloat162float(__float2bfloat16(x.x));
    float h1 = __bfloat162float(__float2bfloat16(x.y));
    float h2 = __bfloat162float(__float2bfloat16(x.z));
    float h3 = __bfloat162float(__float2bfloat16(x.w));
    *(uint2*)&dh[i] = make_uint2(pack_bf16(h0, h1), pack_bf16(h2, h3));
    *(uint2*)&dl[i] = make_uint2(pack_bf16(x.x - h0, x.y - h1), pack_bf16(x.z - h2, x.w - h3));
}

// ---------------- CSR build (fused edge+vertex) ----------------
__global__ void k_zero_all() {
    int i = blockIdx.x * blockDim.x + threadIdx.x;
    if (i < NEX) g_cnt_e[i] = 0;
    if (i < NVX) g_cnt_v[i] = 0;
}

__global__ void k_hist_all(const int* __restrict__ eidx, const int* __restrict__ vidx) {
    int i = blockIdx.x * blockDim.x + threadIdx.x;
    if (i < PX) {
        atomicAdd(&g_cnt_e[eidx[i]], 1);
        atomicAdd(&g_cnt_v[vidx[i]], 1);
    }
}

__global__ void k_scan_all() {
    const bool EDGE = (blockIdx.x == 0);
    const int n = EDGE ? NEX : NVX;
    const int items = (n + 1023) / 1024;
    const int* cnt = EDGE ? g_cnt_e : g_cnt_v;
    int* off = EDGE ? g_off_e : g_off_v;
    int* cur = EDGE ? g_cur_e : g_cur_v;

    __shared__ int wsum[32];
    int t = threadIdx.x;            // blockDim.x == 1024
    int lane = t & 31, wid = t >> 5;
    int start = t * items;
    int end = min(start + items, n);

    int sum = 0;
    for (int i = start; i < end; i++) sum += cnt[i];

    int v = sum;
#pragma unroll
    for (int s = 1; s < 32; s <<= 1) {
        int y = __shfl_up_sync(0xffffffffu, v, s);
        if (lane >= s) v += y;
    }
    if (lane == 31) wsum[wid] = v;
    __syncthreads();
    if (wid == 0) {
        int w = wsum[lane];
        int vi = w;
#pragma unroll
        for (int s = 1; s < 32; s <<= 1) {
            int y = __shfl_up_sync(0xffffffffu, vi, s);
            if (lane >= s) vi += y;
        }
        wsum[lane] = vi - w;
    }
    __syncthreads();

    int excl = wsum[wid] + (v - sum);
    int run = excl;
    for (int i = start; i < end; i++) {
        off[i] = run;
        cur[i] = run;
        run += cnt[i];
    }
    if (t == 1023) off[n] = run;
}

__global__ void k_fill_all(const int* __restrict__ eidx, const int* __restrict__ vidx) {
    int i = blockIdx.x * blockDim.x + threadIdx.x;
    if (i < PX) {
        int pe = atomicAdd(&g_cur_e[eidx[i]], 1);
        g_perm_e[pe] = i;
        int pv = atomicAdd(&g_cur_v[vidx[i]], 1);
        g_perm_v[pv] = i;
    }
}

// ---------------- split-bf16 tensor-core GEMM, cp.async + ldmatrix ----------
#define BM 128
#define BN 128
#define BK 32
#define SP 20            // smem row stride in b32 (16 data + 4 pad); conflict-free ldmatrix
#define SMEM_BYTES (8 * BM * SP * 4)   // 2 buffers x 4 arrays x BM*SP u32 = 81920B

__device__ __forceinline__ void mma_bf16(float* c, const unsigned* a, const unsigned* b) {
    asm volatile(
        "mma.sync.aligned.m16n8k16.row.col.f32.bf16.bf16.f32 "
        "{%0,%1,%2,%3}, {%4,%5,%6,%7}, {%8,%9}, {%0,%1,%2,%3};"
        : "+f"(c[0]), "+f"(c[1]), "+f"(c[2]), "+f"(c[3])
        : "r"(a[0]), "r"(a[1]), "r"(a[2]), "r"(a[3]), "r"(b[0]), "r"(b[1]));
}

__device__ __forceinline__ void cp16(unsigned* dst, const void* src) {
    unsigned s = (unsigned)__cvta_generic_to_shared(dst);
    asm volatile("cp.async.cg.shared.global [%0], [%1], 16;" :: "r"(s), "l"(src));
}

__device__ __forceinline__ void ldsm4(unsigned* r, const unsigned* p) {
    unsigned a = (unsigned)__cvta_generic_to_shared(p);
    asm volatile("ldmatrix.sync.aligned.m8n8.x4.shared.b16 {%0,%1,%2,%3}, [%4];"
        : "=r"(r[0]), "=r"(r[1]), "=r"(r[2]), "=r"(r[3]) : "r"(a));
}

__device__ __forceinline__ void ldsm2(unsigned* r, const unsigned* p) {
    unsigned a = (unsigned)__cvta_generic_to_shared(p);
    asm volatile("ldmatrix.sync.aligned.m8n8.x2.shared.b16 {%0,%1}, [%2];"
        : "=r"(r[0]), "=r"(r[1]) : "r"(a));
}

template <bool VE>
__global__ void __launch_bounds__(256, 2)
k_gemm_bf16(const float* __restrict__ bias, const float* __restrict__ rowscale, int M) {
    const __nv_bfloat16* __restrict__ Ah = VE ? g_vh : g_eh;
    const __nv_bfloat16* __restrict__ Al = VE ? g_vl : g_el;
    const __nv_bfloat16* __restrict__ Bh = VE ? g_w1h : g_w2h;
    const __nv_bfloat16* __restrict__ Bl = VE ? g_w1l : g_w2l;
    float* C = VE ? g_ve : g_ev;

    extern __shared__ unsigned smem_u[];
    unsigned* sA_hi = smem_u;                    // [2][BM*SP]
    unsigned* sA_lo = smem_u + 2 * BM * SP;
    unsigned* sB_hi = smem_u + 4 * BM * SP;
    unsigned* sB_lo = smem_u + 6 * BM * SP;

    const int tid = threadIdx.x;
    const int bm = blockIdx.x * BM;
    const int bn = blockIdx.y * BN;
    const int wid = tid >> 5, lane = tid & 31;
    const int gid = lane >> 2, tid4 = lane & 3;
    const int wm = (wid & 1) * 64;
    const int wn = (wid >> 1) * 32;

    const int aRow = lane & 15;
    const int aCol = (lane >> 4) * 4;
    const int bRow = lane & 7;
    const int bCol = ((lane >> 3) & 1) * 4;

    const int crow = tid >> 1;
    const int csg = (tid & 1) * 2;
    const int gmc = min(bm + crow, M - 1);
    const size_t aBase = (size_t)gmc * HD + csg * 8;
    const size_t bBase = (size_t)(bn + crow) * HD + csg * 8;
    const int dOff = crow * SP + csg * 4;

    float acc[4][4][4];
#pragma unroll
    for (int mt = 0; mt < 4; mt++)
#pragma unroll
        for (int nt = 0; nt < 4; nt++)
#pragma unroll
            for (int q = 0; q < 4; q++) acc[mt][nt][q] = 0.f;

#define CP_STAGE(KT, BUF)                                                     \
    {                                                                         \
        int bo = (BUF) * BM * SP + dOff;                                      \
        size_t ka = aBase + (KT) * BK;                                        \
        size_t kb = bBase + (KT) * BK;                                        \
        cp16(&sA_hi[bo], Ah + ka);     cp16(&sA_hi[bo + 4], Ah + ka + 8);     \
        cp16(&sA_lo[bo], Al + ka);     cp16(&sA_lo[bo + 4], Al + ka + 8);     \
        cp16(&sB_hi[bo], Bh + kb);     cp16(&sB_hi[bo + 4], Bh + kb + 8);     \
        cp16(&sB_lo[bo], Bl + kb);     cp16(&sB_lo[bo + 4], Bl + kb + 8);     \
    }

#define COMPUTE_TILE(BUF)                                                     \
    {                                                                         \
        const unsigned* pAh = sA_hi + (BUF) * BM * SP;                        \
        const unsigned* pAl = sA_lo + (BUF) * BM * SP;                        \
        const unsigned* pBh = sB_hi + (BUF) * BM * SP;                        \
        const unsigned* pBl = sB_lo + (BUF) * BM * SP;                        \
        _Pragma("unroll")                                                     \
        for (int ks = 0; ks < 2; ks++) {                                      \
            unsigned ah[4][4], al[4][4];                                      \
            _Pragma("unroll")                                                 \
            for (int mt = 0; mt < 4; mt++) {                                  \
                int ao = (wm + mt * 16 + aRow) * SP + ks * 8 + aCol;          \
                ldsm4(ah[mt], pAh + ao);                                      \
                ldsm4(al[mt], pAl + ao);                                      \
            }                                                                 \
            _Pragma("unroll")                                                 \
            for (int nt = 0; nt < 4; nt++) {                                  \
                int bo2 = (wn + nt * 8 + bRow) * SP + ks * 8 + bCol;          \
                unsigned bh[2], bl[2];                                        \
                ldsm2(bh, pBh + bo2);                                         \
                ldsm2(bl, pBl + bo2);                                         \
                _Pragma("unroll")                                             \
                for (int mt = 0; mt < 4; mt++) {                              \
                    mma_bf16(acc[mt][nt], ah[mt], bh);                        \
                    mma_bf16(acc[mt][nt], ah[mt], bl);                        \
                    mma_bf16(acc[mt][nt], al[mt], bh);                        \
                }                                                             \
            }                                                                 \
        }                                                                     \
    }

    CP_STAGE(0, 0);
    asm volatile("cp.async.commit_group;");
#pragma unroll
    for (int kt = 0; kt < HD / BK; kt++) {
        if (kt + 1 < HD / BK) CP_STAGE(kt + 1, (kt + 1) & 1);
        asm volatile("cp.async.commit_group;");
        asm volatile("cp.async.wait_group 1;");
        __syncthreads();
        COMPUTE_TILE(kt & 1);
        __syncthreads();
    }

#undef CP_STAGE
#undef COMPUTE_TILE

    // ---- epilogue: bias + relu + rowscale ----
#pragma unroll
    for (int mt = 0; mt < 4; mt++) {
        int rm0 = bm + wm + mt * 16 + gid;
        int rm1 = rm0 + 8;
        float sc0 = (rm0 < M) ? rowscale[rm0] : 0.f;
        float sc1 = (rm1 < M) ? rowscale[rm1] : 0.f;
#pragma unroll
        for (int nt = 0; nt < 4; nt++) {
            int cn = bn + wn + nt * 8 + tid4 * 2;
            float b0f = bias[cn], b1f = bias[cn + 1];
            if (rm0 < M) {
                float2 o;
                o.x = fmaxf(acc[mt][nt][0] + b0f, 0.f) * sc0;
                o.y = fmaxf(acc[mt][nt][1] + b1f, 0.f) * sc0;
                *(float2*)&C[(size_t)rm0 * HD + cn] = o;
            }
            if (rm1 < M) {
                float2 o;
                o.x = fmaxf(acc[mt][nt][2] + b0f, 0.f) * sc1;
                o.y = fmaxf(acc[mt][nt][3] + b1f, 0.f) * sc1;
                *(float2*)&C[(size_t)rm1 * HD + cn] = o;
            }
        }
    }
}

// ---------------- warp-per-row pull-based accumulation (no smem, no barriers) ----
// Gather loads use __ldcg: working sets (51MB/10MB) are L2-resident but >> L1,
// so L1 allocation is pure thrash on the dominant traffic stream.
__global__ void k_edge_accum(const float* __restrict__ e, const int* __restrict__ pairs_v,
                             const float* __restrict__ nrw, const float* __restrict__ ers,
                             float* __restrict__ e_out) {
    int j = (blockIdx.x * blockDim.x + threadIdx.x) >> 5;
    int lane = threadIdx.x & 31;
    if (j >= NEX) return;
    int s = g_off_e[j], t = g_off_e[j + 1];

    const float4* e4 = (const float4*)&e[(size_t)j * HD];
    float4 a0 = e4[lane * 2], a1 = e4[lane * 2 + 1];

    for (int c = s; c < t; c += 32) {
        int i = c + lane;
        int row = 0; float w = 0.f;
        if (i < t) {
            int p = g_perm_e[i];
            row = pairs_v[p];
            w = nrw[p];
        }
        int m = min(32, t - c);
#pragma unroll 4
        for (int q = 0; q < m; q++) {
            int r = __shfl_sync(0xffffffffu, row, q);
            float wq = __shfl_sync(0xffffffffu, w, q);
            const float4* src = (const float4*)&g_ve[(size_t)r * HD];
            float4 x0 = __ldcg(&src[lane * 2]);
            float4 x1 = __ldcg(&src[lane * 2 + 1]);
            a0.x = fmaf(x0.x, wq, a0.x); a0.y = fmaf(x0.y, wq, a0.y);
            a0.z = fmaf(x0.z, wq, a0.z); a0.w = fmaf(x0.w, wq, a0.w);
            a1.x = fmaf(x1.x, wq, a1.x); a1.y = fmaf(x1.y, wq, a1.y);
            a1.z = fmaf(x1.z, wq, a1.z); a1.w = fmaf(x1.w, wq, a1.w);
        }
    }

    float inv = 1.f / ers[j];
    a0.x *= inv; a0.y *= inv; a0.z *= inv; a0.w *= inv;
    a1.x *= inv; a1.y *= inv; a1.z *= inv; a1.w *= inv;

    float4* o4 = (float4*)&e_out[(size_t)j * HD];
    o4[lane * 2] = a0; o4[lane * 2 + 1] = a1;

    // bf16 hi/lo split for GEMM2 input
    float h[8] = {a0.x, a0.y, a0.z, a0.w, a1.x, a1.y, a1.z, a1.w};
    float hr[8];
#pragma unroll
    for (int q = 0; q < 8; q++) hr[q] = __bfloat162float(__float2bfloat16(h[q]));
    uint4 hv = make_uint4(pack_bf16(h[0], h[1]), pack_bf16(h[2], h[3]),
                          pack_bf16(h[4], h[5]), pack_bf16(h[6], h[7]));
    uint4 lv = make_uint4(pack_bf16(h[0] - hr[0], h[1] - hr[1]),
                          pack_bf16(h[2] - hr[2], h[3] - hr[3]),
                          pack_bf16(h[4] - hr[4], h[5] - hr[5]),
                          pack_bf16(h[6] - hr[6], h[7] - hr[7]));
    *(uint4*)&g_eh[(size_t)j * HD + lane * 8] = hv;
    *(uint4*)&g_el[(size_t)j * HD + lane * 8] = lv;
}

__global__ void k_vertex_accum(const float* __restrict__ v, const int* __restrict__ pairs_e,
                               const float* __restrict__ erw, const float* __restrict__ nrs,
                               const float* __restrict__ nw, float* __restrict__ v_out) {
    int i0 = (blockIdx.x * blockDim.x + threadIdx.x) >> 5;
    int lane = threadIdx.x & 31;
    if (i0 >= NVX) return;
    int s = g_off_v[i0], t = g_off_v[i0 + 1];

    float nwi = nw[i0];
    const float4* v4 = (const float4*)&v[(size_t)i0 * HD];
    float4 a0 = v4[lane * 2], a1 = v4[lane * 2 + 1];
    a0.x *= nwi; a0.y *= nwi; a0.z *= nwi; a0.w *= nwi;
    a1.x *= nwi; a1.y *= nwi; a1.z *= nwi; a1.w *= nwi;

    for (int c = s; c < t; c += 32) {
        int i = c + lane;
        int row = 0; float w = 0.f;
        if (i < t) {
            int p = g_perm_v[i];
            row = pairs_e[p];
            w = erw[p];
        }
        int m = min(32, t - c);
#pragma unroll 4
        for (int q = 0; q < m; q++) {
            int r = __shfl_sync(0xffffffffu, row, q);
            float wq = __shfl_sync(0xffffffffu, w, q);
            const float4* src = (const float4*)&g_ev[(size_t)r * HD];
            float4 x0 = __ldcg(&src[lane * 2]);
            float4 x1 = __ldcg(&src[lane * 2 + 1]);
            a0.x = fmaf(x0.x, wq, a0.x); a0.y = fmaf(x0.y, wq, a0.y);
            a0.z = fmaf(x0.z, wq, a0.z); a0.w = fmaf(x0.w, wq, a0.w);
            a1.x = fmaf(x1.x, wq, a1.x); a1.y = fmaf(x1.y, wq, a1.y);
            a1.z = fmaf(x1.z, wq, a1.z); a1.w = fmaf(x1.w, wq, a1.w);
        }
    }

    float inv = 1.f / nrs[i0];
    a0.x *= inv; a0.y *= inv; a0.z *= inv; a0.w *= inv;
    a1.x *= inv; a1.y *= inv; a1.z *= inv; a1.w *= inv;

    float4* o4 = (float4*)&v_out[(size_t)i0 * HD];
    o4[lane * 2] = a0; o4[lane * 2 + 1] = a1;
}

// ---------------- launcher: R6 fork/join topology (best measured), launches only ----
static cudaStream_t g_s1 = nullptr;
static cudaEvent_t g_evFork = nullptr, g_evCsr = nullptr;

extern "C" void kernel_launch(void* const* d_in, const int* in_sizes, int n_in,
                              void* d_out, int out_size) {
    const float* v            = (const float*)d_in[0];
    const float* e            = (const float*)d_in[1];
    const float* W1           = (const float*)d_in[2];
    const float* b1           = (const float*)d_in[3];
    const float* W2           = (const float*)d_in[4];
    const float* b2           = (const float*)d_in[5];
    const float* n_weight     = (const float*)d_in[6];
    const float* e_weight     = (const float*)d_in[7];
    const float* n_reg_weight = (const float*)d_in[8];
    const float* e_reg_weight = (const float*)d_in[9];
    const float* e_reg_sum    = (const float*)d_in[10];
    const float* n_reg_sum    = (const float*)d_in[11];
    const int*   pairs_v      = (const int*)d_in[12];
    const int*   eidx         = (const int*)d_in[13];
    const int*   pairs_e      = (const int*)d_in[14];
    const int*   vidx         = (const int*)d_in[15];

    float* v_out = (float*)d_out;                              // [NVX, HD]
    float* e_out = (float*)d_out + (size_t)NVX * HD;           // [NEX, HD]

    if (!g_s1) {   // one-time setup on the uncaptured correctness call
        cudaStreamCreateWithFlags(&g_s1, cudaStreamNonBlocking);
        cudaEventCreateWithFlags(&g_evFork, cudaEventDisableTiming);
        cudaEventCreateWithFlags(&g_evCsr, cudaEventDisableTiming);
        cudaFuncSetAttribute(k_gemm_bf16<true>,
                             cudaFuncAttributeMaxDynamicSharedMemorySize, SMEM_BYTES);
        cudaFuncSetAttribute(k_gemm_bf16<false>,
                             cudaFuncAttributeMaxDynamicSharedMemorySize, SMEM_BYTES);
    }

    // main: operand splits (GEMM1 prerequisites)
    k_split_v<<<(NVX * HD / 4 + 255) / 256, 256>>>(v);                       // #1
    k_split_w<<<(2 * HD * HD / 4 + 255) / 256, 256>>>(W1, W2);               // #2

    // fork CSR chain onto s1
    cudaEventRecord(g_evFork, 0);
    cudaStreamWaitEvent(g_s1, g_evFork, 0);
    k_zero_all<<<(NVX + 255) / 256, 256, 0, g_s1>>>();                       // #3

    // GEMM1 (4th submitted launch -> ncu sample window)
    dim3 g1((NVX + BM - 1) / BM, HD / BN);
    k_gemm_bf16<true><<<g1, 256, SMEM_BYTES>>>(b1, n_weight, NVX);           // #4

    k_hist_all<<<(PX + 255) / 256, 256, 0, g_s1>>>(eidx, vidx);              // #5
    k_scan_all<<<2, 1024, 0, g_s1>>>();                                      // #6
    k_fill_all<<<(PX + 255) / 256, 256, 0, g_s1>>>(eidx, vidx);              // #7

    // join CSR into main before the accums
    cudaEventRecord(g_evCsr, g_s1);
    cudaStreamWaitEvent(0, g_evCsr, 0);

    k_edge_accum<<<(NEX + 7) / 8, 256>>>(e, pairs_v, n_reg_weight, e_reg_sum, e_out);   // #8

    dim3 g2((NEX + BM - 1) / BM, HD / BN);
    k_gemm_bf16<false><<<g2, 256, SMEM_BYTES>>>(b2, e_weight, NEX);          // #9

    k_vertex_accum<<<(NVX + 7) / 8, 256>>>(v, pairs_e, e_reg_weight, n_reg_sum, n_weight, v_out); // #10
}

// round 10
// speedup vs baseline: 1.7099x; 1.1195x over previous
#include <cuda_runtime.h>
#include <cuda_bf16.h>

#define NVX 50000
#define NEX 10000
#define HD  256
#define PX  400000

// ---------------- scratch (static device globals; no runtime alloc) ----------------
__device__ float g_ve[(size_t)NVX * HD];   // relu(v @ W1^T + b1) * n_weight
__device__ float g_ev[(size_t)NEX * HD];   // relu(e_out @ W2^T + b2) * e_weight
__device__ __nv_bfloat16 g_vh[(size_t)NVX * HD], g_vl[(size_t)NVX * HD];  // split of v
__device__ __nv_bfloat16 g_eh[(size_t)NEX * HD], g_el[(size_t)NEX * HD];  // split of e_out
__device__ __nv_bfloat16 g_w1h[HD * HD], g_w1l[HD * HD];
__device__ __nv_bfloat16 g_w2h[HD * HD], g_w2l[HD * HD];
__device__ int g_cnt_e[NEX];
__device__ int g_off_e[NEX + 1];
__device__ int g_cur_e[NEX];
__device__ int g_perm_e[PX];
__device__ int g_cnt_v[NVX];
__device__ int g_off_v[NVX + 1];
__device__ int g_cur_v[NVX];
__device__ int g_perm_v[PX];

__device__ __forceinline__ unsigned pack_bf16(float x0, float x1) {
    __nv_bfloat16 h0 = __float2bfloat16(x0);
    __nv_bfloat16 h1 = __float2bfloat16(x1);
    return (unsigned)__bfloat16_as_ushort(h0) | ((unsigned)__bfloat16_as_ushort(h1) << 16);
}

// ---------------- operand split passes ----------------
__global__ void k_split_v(const float* __restrict__ v) {
    size_t i = ((size_t)blockIdx.x * blockDim.x + threadIdx.x) * 4;
    if (i >= (size_t)NVX * HD) return;
    float4 x = *(const float4*)&v[i];
    float h0 = __bfloat162float(__float2bfloat16(x.x));
    float h1 = __bfloat162float(__float2bfloat16(x.y));
    float h2 = __bfloat162float(__float2bfloat16(x.z));
    float h3 = __bfloat162float(__float2bfloat16(x.w));
    uint2 hi = make_uint2(pack_bf16(h0, h1), pack_bf16(h2, h3));
    uint2 lo = make_uint2(pack_bf16(x.x - h0, x.y - h1), pack_bf16(x.z - h2, x.w - h3));
    *(uint2*)&g_vh[i] = hi;
    *(uint2*)&g_vl[i] = lo;
}

__global__ void k_split_w(const float* __restrict__ W1, const float* __restrict__ W2) {
    int t = blockIdx.x * blockDim.x + threadIdx.x;          // 0 .. 2*HD*HD/4-1
    const int per = HD * HD / 4;
    const float* src = (t < per) ? W1 : W2;
    __nv_bfloat16* dh = (t < per) ? g_w1h : g_w2h;
    __nv_bfloat16* dl = (t < per) ? g_w1l : g_w2l;
    size_t i = (size_t)(t < per ? t : t - per) * 4;
    float4 x = *(const float4*)&src[i];
    float h0 = __bfloat162float(__float2bfloat16(x.x));
    float h1 = __bfloat162float(__float2bfloat16(x.y));
    float h2 = __bfloat162float(__float2bfloat16(x.z));
    float h3 = __bfloat162float(__float2bfloat16(x.w));
    *(uint2*)&dh[i] = make_uint2(pack_bf16(h0, h1), pack_bf16(h2, h3));
    *(uint2*)&dl[i] = make_uint2(pack_bf16(x.x - h0, x.y - h1), pack_bf16(x.z - h2, x.w - h3));
}

// ---------------- CSR build (fused edge+vertex) ----------------
__global__ void k_zero_all() {
    int i = blockIdx.x * blockDim.x + threadIdx.x;
    if (i < NEX) g_cnt_e[i] = 0;
    if (i < NVX) g_cnt_v[i] = 0;
}

__global__ void k_hist_all(const int* __restrict__ eidx, const int* __restrict__ vidx) {
    int i = blockIdx.x * blockDim.x + threadIdx.x;
    if (i < PX) {
        atomicAdd(&g_cnt_e[eidx[i]], 1);
        atomicAdd(&g_cnt_v[vidx[i]], 1);
    }
}

__global__ void k_scan_all() {
    const bool EDGE = (blockIdx.x == 0);
    const int n = EDGE ? NEX : NVX;
    const int items = (n + 1023) / 1024;
    const int* cnt = EDGE ? g_cnt_e : g_cnt_v;
    int* off = EDGE ? g_off_e : g_off_v;
    int* cur = EDGE ? g_cur_e : g_cur_v;

    __shared__ int wsum[32];
    int t = threadIdx.x;            // blockDim.x == 1024
    int lane = t & 31, wid = t >> 5;
    int start = t * items;
    int end = min(start + items, n);

    int sum = 0;
    for (int i = start; i < end; i++) sum += cnt[i];

    int v = sum;
#pragma unroll
    for (int s = 1; s < 32; s <<= 1) {
        int y = __shfl_up_sync(0xffffffffu, v, s);
        if (lane >= s) v += y;
    }
    if (lane == 31) wsum[wid] = v;
    __syncthreads();
    if (wid == 0) {
        int w = wsum[lane];
        int vi = w;
#pragma unroll
        for (int s = 1; s < 32; s <<= 1) {
            int y = __shfl_up_sync(0xffffffffu, vi, s);
            if (lane >= s) vi += y;
        }
        wsum[lane] = vi - w;
    }
    __syncthreads();

    int excl = wsum[wid] + (v - sum);
    int run = excl;
    for (int i = start; i < end; i++) {
        off[i] = run;
        cur[i] = run;
        run += cnt[i];
    }
    if (t == 1023) off[n] = run;
}

__global__ void k_fill_all(const int* __restrict__ eidx, const int* __restrict__ vidx) {
    int i = blockIdx.x * blockDim.x + threadIdx.x;
    if (i < PX) {
        int pe = atomicAdd(&g_cur_e[eidx[i]], 1);
        g_perm_e[pe] = i;
        int pv = atomicAdd(&g_cur_v[vidx[i]], 1);
        g_perm_v[pv] = i;
    }
}

// ---------------- split-bf16 tensor-core GEMM, cp.async + ldmatrix ----------
#define BM 128
#define BN 128
#define BK 32
#define SP 20            // smem row stride in b32 (16 data + 4 pad); conflict-free ldmatrix
#define SMEM_BYTES (8 * BM * SP * 4)   // 2 buffers x 4 arrays x BM*SP u32 = 81920B

__device__ __forceinline__ void mma_bf16(float* c, const unsigned* a, const unsigned* b) {
    asm volatile(
        "mma.sync.aligned.m16n8k16.row.col.f32.bf16.bf16.f32 "
        "{%0,%1,%2,%3}, {%4,%5,%6,%7}, {%8,%9}, {%0,%1,%2,%3};"
        : "+f"(c[0]), "+f"(c[1]), "+f"(c[2]), "+f"(c[3])
        : "r"(a[0]), "r"(a[1]), "r"(a[2]), "r"(a[3]), "r"(b[0]), "r"(b[1]));
}

__device__ __forceinline__ void cp16(unsigned* dst, const void* src) {
    unsigned s = (unsigned)__cvta_generic_to_shared(dst);
    asm volatile("cp.async.cg.shared.global [%0], [%1], 16;" :: "r"(s), "l"(src));
}

__device__ __forceinline__ void ldsm4(unsigned* r, const unsigned* p) {
    unsigned a = (unsigned)__cvta_generic_to_shared(p);
    asm volatile("ldmatrix.sync.aligned.m8n8.x4.shared.b16 {%0,%1,%2,%3}, [%4];"
        : "=r"(r[0]), "=r"(r[1]), "=r"(r[2]), "=r"(r[3]) : "r"(a));
}

__device__ __forceinline__ void ldsm2(unsigned* r, const unsigned* p) {
    unsigned a = (unsigned)__cvta_generic_to_shared(p);
    asm volatile("ldmatrix.sync.aligned.m8n8.x2.shared.b16 {%0,%1}, [%2];"
        : "=r"(r[0]), "=r"(r[1]) : "r"(a));
}

template <bool VE>
__global__ void __launch_bounds__(256, 2)
k_gemm_bf16(const float* __restrict__ bias, const float* __restrict__ rowscale, int M) {
    const __nv_bfloat16* __restrict__ Ah = VE ? g_vh : g_eh;
    const __nv_bfloat16* __restrict__ Al = VE ? g_vl : g_el;
    const __nv_bfloat16* __restrict__ Bh = VE ? g_w1h : g_w2h;
    const __nv_bfloat16* __restrict__ Bl = VE ? g_w1l : g_w2l;
    float* C = VE ? g_ve : g_ev;

    extern __shared__ unsigned smem_u[];
    unsigned* sA_hi = smem_u;                    // [2][BM*SP]
    unsigned* sA_lo = smem_u + 2 * BM * SP;
    unsigned* sB_hi = smem_u + 4 * BM * SP;
    unsigned* sB_lo = smem_u + 6 * BM * SP;

    const int tid = threadIdx.x;
    const int bm = blockIdx.x * BM;
    const int bn = blockIdx.y * BN;
    const int wid = tid >> 5, lane = tid & 31;
    const int gid = lane >> 2, tid4 = lane & 3;
    const int wm = (wid & 1) * 64;
    const int wn = (wid >> 1) * 32;

    const int aRow = lane & 15;
    const int aCol = (lane >> 4) * 4;
    const int bRow = lane & 7;
    const int bCol = ((lane >> 3) & 1) * 4;

    const int crow = tid >> 1;
    const int csg = (tid & 1) * 2;
    const int gmc = min(bm + crow, M - 1);
    const size_t aBase = (size_t)gmc * HD + csg * 8;
    const size_t bBase = (size_t)(bn + crow) * HD + csg * 8;
    const int dOff = crow * SP + csg * 4;

    float acc[4][4][4];
#pragma unroll
    for (int mt = 0; mt < 4; mt++)
#pragma unroll
        for (int nt = 0; nt < 4; nt++)
#pragma unroll
            for (int q = 0; q < 4; q++) acc[mt][nt][q] = 0.f;

#define CP_STAGE(KT, BUF)                                                     \
    {                                                                         \
        int bo = (BUF) * BM * SP + dOff;                                      \
        size_t ka = aBase + (KT) * BK;                                        \
        size_t kb = bBase + (KT) * BK;                                        \
        cp16(&sA_hi[bo], Ah + ka);     cp16(&sA_hi[bo + 4], Ah + ka + 8);     \
        cp16(&sA_lo[bo], Al + ka);     cp16(&sA_lo[bo + 4], Al + ka + 8);     \
        cp16(&sB_hi[bo], Bh + kb);     cp16(&sB_hi[bo + 4], Bh + kb + 8);     \
        cp16(&sB_lo[bo], Bl + kb);     cp16(&sB_lo[bo + 4], Bl + kb + 8);     \
    }

#define COMPUTE_TILE(BUF)                                                     \
    {                                                                         \
        const unsigned* pAh = sA_hi + (BUF) * BM * SP;                        \
        const unsigned* pAl = sA_lo + (BUF) * BM * SP;                        \
        const unsigned* pBh = sB_hi + (BUF) * BM * SP;                        \
        const unsigned* pBl = sB_lo + (BUF) * BM * SP;                        \
        _Pragma("unroll")                                                     \
        for (int ks = 0; ks < 2; ks++) {                                      \
            unsigned ah[4][4], al[4][4];                                      \
            _Pragma("unroll")                                                 \
            for (int mt = 0; mt < 4; mt++) {                                  \
                int ao = (wm + mt * 16 + aRow) * SP + ks * 8 + aCol;          \
                ldsm4(ah[mt], pAh + ao);                                      \
                ldsm4(al[mt], pAl + ao);                                      \
            }                                                                 \
            _Pragma("unroll")                                                 \
            for (int nt = 0; nt < 4; nt++) {                                  \
                int bo2 = (wn + nt * 8 + bRow) * SP + ks * 8 + bCol;          \
                unsigned bh[2], bl[2];                                        \
                ldsm2(bh, pBh + bo2);                                         \
                ldsm2(bl, pBl + bo2);                                         \
                _Pragma("unroll")                                             \
                for (int mt = 0; mt < 4; mt++) {                              \
                    mma_bf16(acc[mt][nt], ah[mt], bh);                        \
                    mma_bf16(acc[mt][nt], ah[mt], bl);                        \
                    mma_bf16(acc[mt][nt], al[mt], bh);                        \
                }                                                             \
            }                                                                 \
        }                                                                     \
    }

    CP_STAGE(0, 0);
    asm volatile("cp.async.commit_group;");
#pragma unroll
    for (int kt = 0; kt < HD / BK; kt++) {
        if (kt + 1 < HD / BK) CP_STAGE(kt + 1, (kt + 1) & 1);
        asm volatile("cp.async.commit_group;");
        asm volatile("cp.async.wait_group 1;");
        __syncthreads();
        COMPUTE_TILE(kt & 1);
        __syncthreads();
    }

#undef CP_STAGE
#undef COMPUTE_TILE

    // ---- epilogue: bias + relu + rowscale ----
#pragma unroll
    for (int mt = 0; mt < 4; mt++) {
        int rm0 = bm + wm + mt * 16 + gid;
        int rm1 = rm0 + 8;
        float sc0 = (rm0 < M) ? rowscale[rm0] : 0.f;
        float sc1 = (rm1 < M) ? rowscale[rm1] : 0.f;
#pragma unroll
        for (int nt = 0; nt < 4; nt++) {
            int cn = bn + wn + nt * 8 + tid4 * 2;
            float b0f = bias[cn], b1f = bias[cn + 1];
            if (rm0 < M) {
                float2 o;
                o.x = fmaxf(acc[mt][nt][0] + b0f, 0.f) * sc0;
                o.y = fmaxf(acc[mt][nt][1] + b1f, 0.f) * sc0;
                *(float2*)&C[(size_t)rm0 * HD + cn] = o;
            }
            if (rm1 < M) {
                float2 o;
                o.x = fmaxf(acc[mt][nt][2] + b0f, 0.f) * sc1;
                o.y = fmaxf(acc[mt][nt][3] + b1f, 0.f) * sc1;
                *(float2*)&C[(size_t)rm1 * HD + cn] = o;
            }
        }
    }
}

// ---------------- warp-per-row pull-based accumulation (dense-sector version) ----
// Lane l owns cols [4l,4l+4) and [128+4l,128+4l+4): each LDG.128 warp op covers
// one dense 512B range (100% sector utilization). __ldcg keeps L1 out of the way.
__global__ void k_edge_accum(const float* __restrict__ e, const int* __restrict__ pairs_v,
                             const float* __restrict__ nrw, const float* __restrict__ ers,
                             float* __restrict__ e_out) {
    int j = (blockIdx.x * blockDim.x + threadIdx.x) >> 5;
    int lane = threadIdx.x & 31;
    if (j >= NEX) return;
    int s = g_off_e[j], t = g_off_e[j + 1];

    const float4* e4 = (const float4*)&e[(size_t)j * HD];
    float4 a0 = e4[lane], a1 = e4[lane + 32];

    for (int c = s; c < t; c += 32) {
        int i = c + lane;
        int row = 0; float w = 0.f;
        if (i < t) {
            int p = g_perm_e[i];
            row = pairs_v[p];
            w = nrw[p];
        }
        int m = min(32, t - c);
#pragma unroll 4
        for (int q = 0; q < m; q++) {
            int r = __shfl_sync(0xffffffffu, row, q);
            float wq = __shfl_sync(0xffffffffu, w, q);
            const float4* src = (const float4*)&g_ve[(size_t)r * HD];
            float4 x0 = __ldcg(&src[lane]);
            float4 x1 = __ldcg(&src[lane + 32]);
            a0.x = fmaf(x0.x, wq, a0.x); a0.y = fmaf(x0.y, wq, a0.y);
            a0.z = fmaf(x0.z, wq, a0.z); a0.w = fmaf(x0.w, wq, a0.w);
            a1.x = fmaf(x1.x, wq, a1.x); a1.y = fmaf(x1.y, wq, a1.y);
            a1.z = fmaf(x1.z, wq, a1.z); a1.w = fmaf(x1.w, wq, a1.w);
        }
    }

    float inv = 1.f / ers[j];
    a0.x *= inv; a0.y *= inv; a0.z *= inv; a0.w *= inv;
    a1.x *= inv; a1.y *= inv; a1.z *= inv; a1.w *= inv;

    float4* o4 = (float4*)&e_out[(size_t)j * HD];
    o4[lane] = a0; o4[lane + 32] = a1;

    // bf16 hi/lo split for GEMM2 input (dense uint2 stores at 8B stride)
    float h0a = __bfloat162float(__float2bfloat16(a0.x));
    float h1a = __bfloat162float(__float2bfloat16(a0.y));
    float h2a = __bfloat162float(__float2bfloat16(a0.z));
    float h3a = __bfloat162float(__float2bfloat16(a0.w));
    float h0b = __bfloat162float(__float2bfloat16(a1.x));
    float h1b = __bfloat162float(__float2bfloat16(a1.y));
    float h2b = __bfloat162float(__float2bfloat16(a1.z));
    float h3b = __bfloat162float(__float2bfloat16(a1.w));
    *(uint2*)&g_eh[(size_t)j * HD + 4 * lane] =
        make_uint2(pack_bf16(a0.x, a0.y), pack_bf16(a0.z, a0.w));
    *(uint2*)&g_eh[(size_t)j * HD + 128 + 4 * lane] =
        make_uint2(pack_bf16(a1.x, a1.y), pack_bf16(a1.z, a1.w));
    *(uint2*)&g_el[(size_t)j * HD + 4 * lane] =
        make_uint2(pack_bf16(a0.x - h0a, a0.y - h1a), pack_bf16(a0.z - h2a, a0.w - h3a));
    *(uint2*)&g_el[(size_t)j * HD + 128 + 4 * lane] =
        make_uint2(pack_bf16(a1.x - h0b, a1.y - h1b), pack_bf16(a1.z - h2b, a1.w - h3b));
}

__global__ void k_vertex_accum(const float* __restrict__ v, const int* __restrict__ pairs_e,
                               const float* __restrict__ erw, const float* __restrict__ nrs,
                               const float* __restrict__ nw, float* __restrict__ v_out) {
    int i0 = (blockIdx.x * blockDim.x + threadIdx.x) >> 5;
    int lane = threadIdx.x & 31;
    if (i0 >= NVX) return;
    int s = g_off_v[i0], t = g_off_v[i0 + 1];

    float nwi = nw[i0];
    const float4* v4 = (const float4*)&v[(size_t)i0 * HD];
    float4 a0 = v4[lane], a1 = v4[lane + 32];
    a0.x *= nwi; a0.y *= nwi; a0.z *= nwi; a0.w *= nwi;
    a1.x *= nwi; a1.y *= nwi; a1.z *= nwi; a1.w *= nwi;

    for (int c = s; c < t; c += 32) {
        int i = c + lane;
        int row = 0; float w = 0.f;
        if (i < t) {
            int p = g_perm_v[i];
            row = pairs_e[p];
            w = erw[p];
        }
        int m = min(32, t - c);
#pragma unroll 4
        for (int q = 0; q < m; q++) {
            int r = __shfl_sync(0xffffffffu, row, q);
            float wq = __shfl_sync(0xffffffffu, w, q);
            const float4* src = (const float4*)&g_ev[(size_t)r * HD];
            float4 x0 = __ldcg(&src[lane]);
            float4 x1 = __ldcg(&src[lane + 32]);
            a0.x = fmaf(x0.x, wq, a0.x); a0.y = fmaf(x0.y, wq, a0.y);
            a0.z = fmaf(x0.z, wq, a0.z); a0.w = fmaf(x0.w, wq, a0.w);
            a1.x = fmaf(x1.x, wq, a1.x); a1.y = fmaf(x1.y, wq, a1.y);
            a1.z = fmaf(x1.z, wq, a1.z); a1.w = fmaf(x1.w, wq, a1.w);
        }
    }

    float inv = 1.f / nrs[i0];
    a0.x *= inv; a0.y *= inv; a0.z *= inv; a0.w *= inv;
    a1.x *= inv; a1.y *= inv; a1.z *= inv; a1.w *= inv;

    float4* o4 = (float4*)&v_out[(size_t)i0 * HD];
    o4[lane] = a0; o4[lane + 32] = a1;
}

// ---------------- launcher: R6 fork/join topology (best measured), launches only ----
static cudaStream_t g_s1 = nullptr;
static cudaEvent_t g_evFork = nullptr, g_evCsr = nullptr;

extern "C" void kernel_launch(void* const* d_in, const int* in_sizes, int n_in,
                              void* d_out, int out_size) {
    const float* v            = (const float*)d_in[0];
    const float* e            = (const float*)d_in[1];
    const float* W1           = (const float*)d_in[2];
    const float* b1           = (const float*)d_in[3];
    const float* W2           = (const float*)d_in[4];
    const float* b2           = (const float*)d_in[5];
    const float* n_weight     = (const float*)d_in[6];
    const float* e_weight     = (const float*)d_in[7];
    const float* n_reg_weight = (const float*)d_in[8];
    const float* e_reg_weight = (const float*)d_in[9];
    const float* e_reg_sum    = (const float*)d_in[10];
    const float* n_reg_sum    = (const float*)d_in[11];
    const int*   pairs_v      = (const int*)d_in[12];
    const int*   eidx         = (const int*)d_in[13];
    const int*   pairs_e      = (const int*)d_in[14];
    const int*   vidx         = (const int*)d_in[15];

    float* v_out = (float*)d_out;                              // [NVX, HD]
    float* e_out = (float*)d_out + (size_t)NVX * HD;           // [NEX, HD]

    if (!g_s1) {   // one-time setup on the uncaptured correctness call
        cudaStreamCreateWithFlags(&g_s1, cudaStreamNonBlocking);
        cudaEventCreateWithFlags(&g_evFork, cudaEventDisableTiming);
        cudaEventCreateWithFlags(&g_evCsr, cudaEventDisableTiming);
        cudaFuncSetAttribute(k_gemm_bf16<true>,
                             cudaFuncAttributeMaxDynamicSharedMemorySize, SMEM_BYTES);
        cudaFuncSetAttribute(k_gemm_bf16<false>,
                             cudaFuncAttributeMaxDynamicSharedMemorySize, SMEM_BYTES);
    }

    // main: operand splits (GEMM1 prerequisites)
    k_split_v<<<(NVX * HD / 4 + 255) / 256, 256>>>(v);                       // #1
    k_split_w<<<(2 * HD * HD / 4 + 255) / 256, 256>>>(W1, W2);               // #2

    // fork CSR chain onto s1
    cudaEventRecord(g_evFork, 0);
    cudaStreamWaitEvent(g_s1, g_evFork, 0);
    k_zero_all<<<(NVX + 255) / 256, 256, 0, g_s1>>>();                       // #3

    // GEMM1 (4th submitted launch -> ncu sample window)
    dim3 g1((NVX + BM - 1) / BM, HD / BN);
    k_gemm_bf16<true><<<g1, 256, SMEM_BYTES>>>(b1, n_weight, NVX);           // #4

    k_hist_all<<<(PX + 255) / 256, 256, 0, g_s1>>>(eidx, vidx);              // #5
    k_scan_all<<<2, 1024, 0, g_s1>>>();                                      // #6
    k_fill_all<<<(PX + 255) / 256, 256, 0, g_s1>>>(eidx, vidx);              // #7

    // join CSR into main before the accums
    cudaEventRecord(g_evCsr, g_s1);
    cudaStreamWaitEvent(0, g_evCsr, 0);

    k_edge_accum<<<(NEX + 7) / 8, 256>>>(e, pairs_v, n_reg_weight, e_reg_sum, e_out);   // #8

    dim3 g2((NEX + BM - 1) / BM, HD / BN);
    k_gemm_bf16<false><<<g2, 256, SMEM_BYTES>>>(b2, e_weight, NEX);          // #9

    k_vertex_accum<<<(NVX + 7) / 8, 256>>>(v, pairs_e, e_reg_weight, n_reg_sum, n_weight, v_out); // #10
}

// round 11
// speedup vs baseline: 1.7244x; 1.0085x over previous
#include <cuda_runtime.h>
#include <cuda_bf16.h>

#define NVX 50000
#define NEX 10000
#define HD  256
#define PX  400000

// ---------------- scratch (static device globals; no runtime alloc) ----------------
__device__ float g_ve[(size_t)NVX * HD];   // relu(v @ W1^T + b1) * n_weight
__device__ float g_ev[(size_t)NEX * HD];   // relu(e_out @ W2^T + b2) * e_weight
__device__ __nv_bfloat16 g_w1h[HD * HD], g_w1l[HD * HD];
__device__ __nv_bfloat16 g_w2h[HD * HD], g_w2l[HD * HD];
__device__ int g_cnt_e[NEX];
__device__ int g_off_e[NEX + 1];
__device__ int g_cur_e[NEX];
__device__ int g_perm_e[PX];
__device__ int g_cnt_v[NVX];
__device__ int g_off_v[NVX + 1];
__device__ int g_cur_v[NVX];
__device__ int g_perm_v[PX];

__device__ __forceinline__ unsigned pack_bf16(float x0, float x1) {
    __nv_bfloat16 h0 = __float2bfloat16(x0);
    __nv_bfloat16 h1 = __float2bfloat16(x1);
    return (unsigned)__bfloat16_as_ushort(h0) | ((unsigned)__bfloat16_as_ushort(h1) << 16);
}

// ---------------- weight split pass (tiny: 2x256x256) ----------------
__global__ void k_split_w(const float* __restrict__ W1, const float* __restrict__ W2) {
    int t = blockIdx.x * blockDim.x + threadIdx.x;          // 0 .. 2*HD*HD/4-1
    const int per = HD * HD / 4;
    const float* src = (t < per) ? W1 : W2;
    __nv_bfloat16* dh = (t < per) ? g_w1h : g_w2h;
    __nv_bfloat16* dl = (t < per) ? g_w1l : g_w2l;
    size_t i = (size_t)(t < per ? t : t - per) * 4;
    float4 x = *(const float4*)&src[i];
    float h0 = __bfloat162float(__float2bfloat16(x.x));
    float h1 = __bfloat162float(__float2bfloat16(x.y));
    float h2 = __bfloat162float(__float2bfloat16(x.z));
    float h3 = __bfloat162float(__float2bfloat16(x.w));
    *(uint2*)&dh[i] = make_uint2(pack_bf16(h0, h1), pack_bf16(h2, h3));
    *(uint2*)&dl[i] = make_uint2(pack_bf16(x.x - h0, x.y - h1), pack_bf16(x.z - h2, x.w - h3));
}

// ---------------- CSR build (fused edge+vertex) ----------------
__global__ void k_zero_all() {
    int i = blockIdx.x * blockDim.x + threadIdx.x;
    if (i < NEX) g_cnt_e[i] = 0;
    if (i < NVX) g_cnt_v[i] = 0;
}

__global__ void k_hist_all(const int* __restrict__ eidx, const int* __restrict__ vidx) {
    int i = blockIdx.x * blockDim.x + threadIdx.x;
    if (i < PX) {
        atomicAdd(&g_cnt_e[eidx[i]], 1);
        atomicAdd(&g_cnt_v[vidx[i]], 1);
    }
}

__global__ void k_scan_all() {
    const bool EDGE = (blockIdx.x == 0);
    const int n = EDGE ? NEX : NVX;
    const int items = (n + 1023) / 1024;
    const int* cnt = EDGE ? g_cnt_e : g_cnt_v;
    int* off = EDGE ? g_off_e : g_off_v;
    int* cur = EDGE ? g_cur_e : g_cur_v;

    __shared__ int wsum[32];
    int t = threadIdx.x;            // blockDim.x == 1024
    int lane = t & 31, wid = t >> 5;
    int start = t * items;
    int end = min(start + items, n);

    int sum = 0;
    for (int i = start; i < end; i++) sum += cnt[i];

    int v = sum;
#pragma unroll
    for (int s = 1; s < 32; s <<= 1) {
        int y = __shfl_up_sync(0xffffffffu, v, s);
        if (lane >= s) v += y;
    }
    if (lane == 31) wsum[wid] = v;
    __syncthreads();
    if (wid == 0) {
        int w = wsum[lane];
        int vi = w;
#pragma unroll
        for (int s = 1; s < 32; s <<= 1) {
            int y = __shfl_up_sync(0xffffffffu, vi, s);
            if (lane >= s) vi += y;
        }
        wsum[lane] = vi - w;
    }
    __syncthreads();

    int excl = wsum[wid] + (v - sum);
    int run = excl;
    for (int i = start; i < end; i++) {
        off[i] = run;
        cur[i] = run;
        run += cnt[i];
    }
    if (t == 1023) off[n] = run;
}

__global__ void k_fill_all(const int* __restrict__ eidx, const int* __restrict__ vidx) {
    int i = blockIdx.x * blockDim.x + threadIdx.x;
    if (i < PX) {
        int pe = atomicAdd(&g_cur_e[eidx[i]], 1);
        g_perm_e[pe] = i;
        int pv = atomicAdd(&g_cur_v[vidx[i]], 1);
        g_perm_v[pv] = i;
    }
}

// ---------------- split-bf16 tensor-core GEMM with FUSED fp32->hi/lo conversion ----
// C[m,n] = relu(sum_k A[m,k]*B[n,k] + bias[n]) * rowscale[m]
// A read as raw fp32 (cp.async), split to bf16 hi/lo in a per-tile smem convert
// phase; B pre-split. C = Ah*Bh + Ah*Bl + Al*Bh (fp32 accum), ldmatrix + mma.
#define BM 128
#define BN 128
#define BK 32
#define SP 20            // hi/lo smem row stride in u32 (16 data + 4 pad)
#define SP32 36          // fp32 A staging row stride in u32 (32 data + 4 pad)
// smem: A32 2buf (2*128*36*4=36864) + Ahi/Alo 1buf (2*10240) + Bhi/Blo 2buf (4*10240)
#define SMEM_BYTES (36864 + 2 * 10240 + 4 * 10240)   // 98304

__device__ __forceinline__ void mma_bf16(float* c, const unsigned* a, const unsigned* b) {
    asm volatile(
        "mma.sync.aligned.m16n8k16.row.col.f32.bf16.bf16.f32 "
        "{%0,%1,%2,%3}, {%4,%5,%6,%7}, {%8,%9}, {%0,%1,%2,%3};"
        : "+f"(c[0]), "+f"(c[1]), "+f"(c[2]), "+f"(c[3])
        : "r"(a[0]), "r"(a[1]), "r"(a[2]), "r"(a[3]), "r"(b[0]), "r"(b[1]));
}

__device__ __forceinline__ void cp16(unsigned* dst, const void* src) {
    unsigned s = (unsigned)__cvta_generic_to_shared(dst);
    asm volatile("cp.async.cg.shared.global [%0], [%1], 16;" :: "r"(s), "l"(src));
}

__device__ __forceinline__ void ldsm4(unsigned* r, const unsigned* p) {
    unsigned a = (unsigned)__cvta_generic_to_shared(p);
    asm volatile("ldmatrix.sync.aligned.m8n8.x4.shared.b16 {%0,%1,%2,%3}, [%4];"
        : "=r"(r[0]), "=r"(r[1]), "=r"(r[2]), "=r"(r[3]) : "r"(a));
}

__device__ __forceinline__ void ldsm2(unsigned* r, const unsigned* p) {
    unsigned a = (unsigned)__cvta_generic_to_shared(p);
    asm volatile("ldmatrix.sync.aligned.m8n8.x2.shared.b16 {%0,%1}, [%2];"
        : "=r"(r[0]), "=r"(r[1]) : "r"(a));
}

template <bool VE>
__global__ void __launch_bounds__(256, 2)
k_gemm_f32a(const float* __restrict__ A, const float* __restrict__ bias,
            const float* __restrict__ rowscale, int M) {
    const __nv_bfloat16* __restrict__ Bh = VE ? g_w1h : g_w2h;
    const __nv_bfloat16* __restrict__ Bl = VE ? g_w1l : g_w2l;
    float* C = VE ? g_ve : g_ev;

    extern __shared__ unsigned smem_u[];
    unsigned* sA32 = smem_u;                       // [2][128][36] u32 (fp32 tile)
    unsigned* sAhi = smem_u + 9216;                // [128*SP]
    unsigned* sAlo = smem_u + 9216 + 2560;         // [128*SP]
    unsigned* sBhi = smem_u + 9216 + 5120;         // [2][128*SP]
    unsigned* sBlo = smem_u + 9216 + 5120 + 5120;  // [2][128*SP]

    const int tid = threadIdx.x;
    const int bm = blockIdx.x * BM;
    const int bn = blockIdx.y * BN;
    const int wid = tid >> 5, lane = tid & 31;
    const int gid = lane >> 2, tid4 = lane & 3;
    const int wm = (wid & 1) * 64;
    const int wn = (wid >> 1) * 32;

    // ldmatrix per-lane source rows/cols
    const int aRow = lane & 15;
    const int aCol = (lane >> 4) * 4;
    const int bRow = lane & 7;
    const int bCol = ((lane >> 3) & 1) * 4;

    // fp32 A cp.async mapping: thread -> rows {t>>2, t>>2+64}, quads {2(t&3), 2(t&3)+1}
    const int ar0 = tid >> 2;
    const int aq0 = (tid & 3) * 2;
    const int gm0 = min(bm + ar0, M - 1);
    const int gm1 = min(bm + ar0 + 64, M - 1);
    const size_t aB0 = (size_t)gm0 * HD + aq0 * 4;
    const size_t aB1 = (size_t)gm1 * HD + aq0 * 4;

    // B cp.async mapping (pre-split bf16): thread -> row t>>1, 2 x 16-bf16 segs
    const int crow = tid >> 1;
    const int csg = (tid & 1) * 2;
    const size_t bBase = (size_t)(bn + crow) * HD + csg * 8;
    const int dOff = crow * SP + csg * 4;

    float acc[4][4][4];
#pragma unroll
    for (int mt = 0; mt < 4; mt++)
#pragma unroll
        for (int nt = 0; nt < 4; nt++)
#pragma unroll
            for (int q = 0; q < 4; q++) acc[mt][nt][q] = 0.f;

#define CP_A(KT, BUF)                                                         \
    {                                                                         \
        unsigned* d0 = sA32 + ((BUF) * 128 + ar0) * SP32 + aq0 * 4;           \
        unsigned* d1 = sA32 + ((BUF) * 128 + ar0 + 64) * SP32 + aq0 * 4;      \
        cp16(d0,     A + aB0 + (KT) * BK);                                    \
        cp16(d0 + 4, A + aB0 + (KT) * BK + 4);                                \
        cp16(d1,     A + aB1 + (KT) * BK);                                    \
        cp16(d1 + 4, A + aB1 + (KT) * BK + 4);                                \
    }

#define CP_B(KT, BUF)                                                         \
    {                                                                         \
        int bo = (BUF) * BM * SP + dOff;                                      \
        size_t kb = bBase + (KT) * BK;                                        \
        cp16(&sBhi[bo], Bh + kb);     cp16(&sBhi[bo + 4], Bh + kb + 8);       \
        cp16(&sBlo[bo], Bl + kb);     cp16(&sBlo[bo + 4], Bl + kb + 8);       \
    }

#define CONVERT_TILE(BUF)                                                     \
    {                                                                         \
        const unsigned* s32 = sA32 + (BUF) * 128 * SP32;                      \
        int cl = tid & 31, cw = tid >> 5;                                     \
        _Pragma("unroll")                                                     \
        for (int g = 0; g < 2; g++) {                                         \
            int row = (2 * cw + g) * 8 + (cl & 7);                            \
            _Pragma("unroll")                                                 \
            for (int h2 = 0; h2 < 2; h2++) {                                  \
                int quad = (cl >> 3) + 4 * h2;                                \
                float4 f = *(const float4*)&s32[row * SP32 + quad * 4];       \
                unsigned p0 = pack_bf16(f.x, f.y);                            \
                unsigned p1 = pack_bf16(f.z, f.w);                            \
                float hx = __uint_as_float(p0 << 16);                         \
                float hy = __uint_as_float(p0 & 0xffff0000u);                 \
                float hz = __uint_as_float(p1 << 16);                         \
                float hw = __uint_as_float(p1 & 0xffff0000u);                 \
                unsigned q0 = pack_bf16(f.x - hx, f.y - hy);                  \
                unsigned q1 = pack_bf16(f.z - hz, f.w - hw);                  \
                *(uint2*)&sAhi[row * SP + quad * 2] = make_uint2(p0, p1);     \
                *(uint2*)&sAlo[row * SP + quad * 2] = make_uint2(q0, q1);     \
            }                                                                 \
        }                                                                     \
    }

#define COMPUTE_TILE(BUF)                                                     \
    {                                                                         \
        const unsigned* pBh = sBhi + (BUF) * BM * SP;                         \
        const unsigned* pBl = sBlo + (BUF) * BM * SP;                         \
        _Pragma("unroll")                                                     \
        for (int ks = 0; ks < 2; ks++) {                                      \
            unsigned ah[4][4], al[4][4];                                      \
            _Pragma("unroll")                                                 \
            for (int mt = 0; mt < 4; mt++) {                                  \
                int ao = (wm + mt * 16 + aRow) * SP + ks * 8 + aCol;          \
                ldsm4(ah[mt], sAhi + ao);                                     \
                ldsm4(al[mt], sAlo + ao);                                     \
            }                                                                 \
            _Pragma("unroll")                                                 \
            for (int nt = 0; nt < 4; nt++) {                                  \
                int bo2 = (wn + nt * 8 + bRow) * SP + ks * 8 + bCol;          \
                unsigned bh[2], bl[2];                                        \
                ldsm2(bh, pBh + bo2);                                         \
                ldsm2(bl, pBl + bo2);                                         \
                _Pragma("unroll")                                             \
                for (int mt = 0; mt < 4; mt++) {                              \
                    mma_bf16(acc[mt][nt], ah[mt], bh);                        \
                    mma_bf16(acc[mt][nt], ah[mt], bl);                        \
                    mma_bf16(acc[mt][nt], al[mt], bh);                        \
                }                                                             \
            }                                                                 \
        }                                                                     \
    }

    CP_A(0, 0); CP_B(0, 0);
    asm volatile("cp.async.commit_group;");
#pragma unroll
    for (int kt = 0; kt < HD / BK; kt++) {
        if (kt + 1 < HD / BK) { CP_A(kt + 1, (kt + 1) & 1); CP_B(kt + 1, (kt + 1) & 1); }
        asm volatile("cp.async.commit_group;");
        asm volatile("cp.async.wait_group 1;");
        __syncthreads();
        CONVERT_TILE(kt & 1);
        __syncthreads();
        COMPUTE_TILE(kt & 1);
        __syncthreads();
    }

#undef CP_A
#undef CP_B
#undef CONVERT_TILE
#undef COMPUTE_TILE

    // ---- epilogue: bias + relu + rowscale ----
#pragma unroll
    for (int mt = 0; mt < 4; mt++) {
        int rm0 = bm + wm + mt * 16 + gid;
        int rm1 = rm0 + 8;
        float sc0 = (rm0 < M) ? rowscale[rm0] : 0.f;
        float sc1 = (rm1 < M) ? rowscale[rm1] : 0.f;
#pragma unroll
        for (int nt = 0; nt < 4; nt++) {
            int cn = bn + wn + nt * 8 + tid4 * 2;
            float b0f = bias[cn], b1f = bias[cn + 1];
            if (rm0 < M) {
                float2 o;
                o.x = fmaxf(acc[mt][nt][0] + b0f, 0.f) * sc0;
                o.y = fmaxf(acc[mt][nt][1] + b1f, 0.f) * sc0;
                *(float2*)&C[(size_t)rm0 * HD + cn] = o;
            }
            if (rm1 < M) {
                float2 o;
                o.x = fmaxf(acc[mt][nt][2] + b0f, 0.f) * sc1;
                o.y = fmaxf(acc[mt][nt][3] + b1f, 0.f) * sc1;
                *(float2*)&C[(size_t)rm1 * HD + cn] = o;
            }
        }
    }
}

// ---------------- warp-per-row pull-based accumulation (dense sectors, .cg) ----
// e_out[j,:] = (e[j,:] + sum g_ve[pairs_v[p],:]*nrw[p]) / ers[j]
__global__ void k_edge_accum(const float* __restrict__ e, const int* __restrict__ pairs_v,
                             const float* __restrict__ nrw, const float* __restrict__ ers,
                             float* __restrict__ e_out) {
    int j = (blockIdx.x * blockDim.x + threadIdx.x) >> 5;
    int lane = threadIdx.x & 31;
    if (j >= NEX) return;
    int s = g_off_e[j], t = g_off_e[j + 1];

    const float4* e4 = (const float4*)&e[(size_t)j * HD];
    float4 a0 = e4[lane], a1 = e4[lane + 32];

    for (int c = s; c < t; c += 32) {
        int i = c + lane;
        int row = 0; float w = 0.f;
        if (i < t) {
            int p = g_perm_e[i];
            row = pairs_v[p];
            w = nrw[p];
        }
        int m = min(32, t - c);
#pragma unroll 4
        for (int q = 0; q < m; q++) {
            int r = __shfl_sync(0xffffffffu, row, q);
            float wq = __shfl_sync(0xffffffffu, w, q);
            const float4* src = (const float4*)&g_ve[(size_t)r * HD];
            float4 x0 = __ldcg(&src[lane]);
            float4 x1 = __ldcg(&src[lane + 32]);
            a0.x = fmaf(x0.x, wq, a0.x); a0.y = fmaf(x0.y, wq, a0.y);
            a0.z = fmaf(x0.z, wq, a0.z); a0.w = fmaf(x0.w, wq, a0.w);
            a1.x = fmaf(x1.x, wq, a1.x); a1.y = fmaf(x1.y, wq, a1.y);
            a1.z = fmaf(x1.z, wq, a1.z); a1.w = fmaf(x1.w, wq, a1.w);
        }
    }

    float inv = 1.f / ers[j];
    a0.x *= inv; a0.y *= inv; a0.z *= inv; a0.w *= inv;
    a1.x *= inv; a1.y *= inv; a1.z *= inv; a1.w *= inv;

    float4* o4 = (float4*)&e_out[(size_t)j * HD];
    o4[lane] = a0; o4[lane + 32] = a1;
}

__global__ void k_vertex_accum(const float* __restrict__ v, const int* __restrict__ pairs_e,
                               const float* __restrict__ erw, const float* __restrict__ nrs,
                               const float* __restrict__ nw, float* __restrict__ v_out) {
    int i0 = (blockIdx.x * blockDim.x + threadIdx.x) >> 5;
    int lane = threadIdx.x & 31;
    if (i0 >= NVX) return;
    int s = g_off_v[i0], t = g_off_v[i0 + 1];

    float nwi = nw[i0];
    const float4* v4 = (const float4*)&v[(size_t)i0 * HD];
    float4 a0 = v4[lane], a1 = v4[lane + 32];
    a0.x *= nwi; a0.y *= nwi; a0.z *= nwi; a0.w *= nwi;
    a1.x *= nwi; a1.y *= nwi; a1.z *= nwi; a1.w *= nwi;

    for (int c = s; c < t; c += 32) {
        int i = c + lane;
        int row = 0; float w = 0.f;
        if (i < t) {
            int p = g_perm_v[i];
            row = pairs_e[p];
            w = erw[p];
        }
        int m = min(32, t - c);
#pragma unroll 4
        for (int q = 0; q < m; q++) {
            int r = __shfl_sync(0xffffffffu, row, q);
            float wq = __shfl_sync(0xffffffffu, w, q);
            const float4* src = (const float4*)&g_ev[(size_t)r * HD];
            float4 x0 = __ldcg(&src[lane]);
            float4 x1 = __ldcg(&src[lane + 32]);
            a0.x = fmaf(x0.x, wq, a0.x); a0.y = fmaf(x0.y, wq, a0.y);
            a0.z = fmaf(x0.z, wq, a0.z); a0.w = fmaf(x0.w, wq, a0.w);
            a1.x = fmaf(x1.x, wq, a1.x); a1.y = fmaf(x1.y, wq, a1.y);
            a1.z = fmaf(x1.z, wq, a1.z); a1.w = fmaf(x1.w, wq, a1.w);
        }
    }

    float inv = 1.f / nrs[i0];
    a0.x *= inv; a0.y *= inv; a0.z *= inv; a0.w *= inv;
    a1.x *= inv; a1.y *= inv; a1.z *= inv; a1.w *= inv;

    float4* o4 = (float4*)&v_out[(size_t)i0 * HD];
    o4[lane] = a0; o4[lane + 32] = a1;
}

// ---------------- launcher: fork/join two-stream graph, launches only ----------------
static cudaStream_t g_s1 = nullptr;
static cudaEvent_t g_evFork = nullptr, g_evCsr = nullptr;

extern "C" void kernel_launch(void* const* d_in, const int* in_sizes, int n_in,
                              void* d_out, int out_size) {
    const float* v            = (const float*)d_in[0];
    const float* e            = (const float*)d_in[1];
    const float* W1           = (const float*)d_in[2];
    const float* b1           = (const float*)d_in[3];
    const float* W2           = (const float*)d_in[4];
    const float* b2           = (const float*)d_in[5];
    const float* n_weight     = (const float*)d_in[6];
    const float* e_weight     = (const float*)d_in[7];
    const float* n_reg_weight = (const float*)d_in[8];
    const float* e_reg_weight = (const float*)d_in[9];
    const float* e_reg_sum    = (const float*)d_in[10];
    const float* n_reg_sum    = (const float*)d_in[11];
    const int*   pairs_v      = (const int*)d_in[12];
    const int*   eidx         = (const int*)d_in[13];
    const int*   pairs_e      = (const int*)d_in[14];
    const int*   vidx         = (const int*)d_in[15];

    float* v_out = (float*)d_out;                              // [NVX, HD]
    float* e_out = (float*)d_out + (size_t)NVX * HD;           // [NEX, HD]

    if (!g_s1) {   // one-time setup on the uncaptured correctness call
        cudaStreamCreateWithFlags(&g_s1, cudaStreamNonBlocking);
        cudaEventCreateWithFlags(&g_evFork, cudaEventDisableTiming);
        cudaEventCreateWithFlags(&g_evCsr, cudaEventDisableTiming);
        cudaFuncSetAttribute(k_gemm_f32a<true>,
                             cudaFuncAttributeMaxDynamicSharedMemorySize, SMEM_BYTES);
        cudaFuncSetAttribute(k_gemm_f32a<false>,
                             cudaFuncAttributeMaxDynamicSharedMemorySize, SMEM_BYTES);
    }

    // main: weight split (GEMM prerequisite, ~2us)
    k_split_w<<<(2 * HD * HD / 4 + 255) / 256, 256>>>(W1, W2);               // #1 main

    // fork CSR chain onto s1
    cudaEventRecord(g_evFork, 0);
    cudaStreamWaitEvent(g_s1, g_evFork, 0);
    k_zero_all<<<(NVX + 255) / 256, 256, 0, g_s1>>>();                       // #2 s1
    k_hist_all<<<(PX + 255) / 256, 256, 0, g_s1>>>(eidx, vidx);              // #3 s1

    // GEMM1 (4th submitted launch -> ncu sample window); reads v fp32 directly
    dim3 g1((NVX + BM - 1) / BM, HD / BN);
    k_gemm_f32a<true><<<g1, 256, SMEM_BYTES>>>(v, b1, n_weight, NVX);        // #4 main

    k_scan_all<<<2, 1024, 0, g_s1>>>();                                      // #5 s1
    k_fill_all<<<(PX + 255) / 256, 256, 0, g_s1>>>(eidx, vidx);              // #6 s1

    // join CSR into main before the accums
    cudaEventRecord(g_evCsr, g_s1);
    cudaStreamWaitEvent(0, g_evCsr, 0);

    k_edge_accum<<<(NEX + 7) / 8, 256>>>(e, pairs_v, n_reg_weight, e_reg_sum, e_out);   // #7

    // GEMM2 reads e_out fp32 directly (no pre-split pass needed)
    dim3 g2((NEX + BM - 1) / BM, HD / BN);
    k_gemm_f32a<false><<<g2, 256, SMEM_BYTES>>>(e_out, b2, e_weight, NEX);   // #8

    k_vertex_accum<<<(NVX + 7) / 8, 256>>>(v, pairs_e, e_reg_weight, n_reg_sum, n_weight, v_out); // #9
}